// round 5
// baseline (speedup 1.0000x reference)
#include <cuda_runtime.h>
#include <cuda_fp16.h>
#include <stdint.h>
#include <math.h>

#define NB 128
#define NI 1152
#define IC 16                   // i per k_hat CTA
#define ICHUNKS (NI/IC)         // 72
#define ICH2 (ICHUNKS*2)        // 144 (2 islot partials per chunk)
#define SPLIT 4                 // i-splits in routing
#define IPS (NI/SPLIT)          // 288
#define PSTEPS (IPS/16)         // 18 (16 i per CTA-step)

// Scratch (static device globals; no runtime allocation)
__device__ __half   g_hat[(size_t)NB * NI * 256];  // [b][i][n*16+e], 75.5 MB
__device__ float    g_s0p[(size_t)ICH2 * NB * 256];
__device__ float    g_sp1[SPLIT * NB * 256];
__device__ float    g_sp2[SPLIT * NB * 256];
__device__ unsigned g_cnt1[NB];                    // zero-init; reset each run
__device__ unsigned g_cnt2[NB];

// ---- packed f32x2 helpers (Blackwell FFMA2 via PTX) ----
__device__ __forceinline__ uint64_t pk(float a, float b) {
    uint64_t r; asm("mov.b64 %0, {%1,%2};" : "=l"(r) : "f"(a), "f"(b)); return r;
}
__device__ __forceinline__ void unpk(uint64_t v, float& lo, float& hi) {
    asm("mov.b64 {%0,%1}, %2;" : "=f"(lo), "=f"(hi) : "l"(v));
}
__device__ __forceinline__ uint64_t mul2(uint64_t a, uint64_t b) {
    uint64_t r; asm("mul.rn.f32x2 %0, %1, %2;" : "=l"(r) : "l"(a), "l"(b)); return r;
}
__device__ __forceinline__ void fma2(uint64_t& d, uint64_t a, uint64_t b) {
    asm("fma.rn.f32x2 %0, %1, %2, %3;" : "=l"(d) : "l"(a), "l"(b), "l"(d));
}
__device__ __forceinline__ void add2(uint64_t& d, uint64_t a) {
    asm("add.rn.f32x2 %0, %1, %2;" : "=l"(d) : "l"(a), "l"(d));
}

// ---- release/acquire counter ops for intra-kernel CTA-group barrier ----
__device__ __forceinline__ void cnt_arrive(unsigned* c) {
    asm volatile("red.release.gpu.global.add.u32 [%0], 1;" :: "l"(c) : "memory");
}
__device__ __forceinline__ unsigned cnt_ld(unsigned* c) {
    unsigned v;
    asm volatile("ld.acquire.gpu.global.u32 %0, [%1];" : "=r"(v) : "l"(c) : "memory");
    return v;
}

// ---------------------------------------------------------------------------
// k_hat: hat[b,i,n,e] = sum_d x[b,i,d]*W[n,i,e,d], fp16 out, e-pair packed.
// grid (72 i-chunks of 16, 16 b-blocks of 8). 256 threads:
//   t = islot*128 + n*8 + ep  (islot: which of 2 interleaved i's, ep: e-pair)
// One STG.32 (half2) per (b,i) per thread. Also emits iter-0 partials.
// ---------------------------------------------------------------------------
__global__ void __launch_bounds__(256) k_hat(const float* __restrict__ x,
                                             const float* __restrict__ W) {
    __shared__ uint64_t sxs[8][IC][8];   // splat (x,x), 8KB
    const int t  = threadIdx.x;
    const int i0 = blockIdx.x * IC;
    const int b0 = blockIdx.y * 8;

    for (int idx = t; idx < 8 * IC * 8; idx += 256) {
        int bb = idx >> 7, rem = idx & 127;
        int ii = rem >> 3, d = rem & 7;
        float v = x[((size_t)(b0 + bb) * NI + i0 + ii) * 8 + d];
        sxs[bb][ii][d] = pk(v, v);
    }
    __syncthreads();

    const int islot = t >> 7, n = (t >> 3) & 15, ep = t & 7;
    // W[n, i, e, d]: float4 index ((n*NI+i)*16 + e)*2 ; e=2ep,2ep+1 -> 4 consec f4
    const float4* wp = reinterpret_cast<const float4*>(W)
                     + ((size_t)(n * NI + i0 + islot) * 16 + 2 * ep) * 2;

    uint64_t s0[8];
#pragma unroll
    for (int k = 0; k < 8; ++k) s0[k] = 0ull;

    for (int i = islot; i < IC; i += 2) {
        float4 wa0 = wp[0], wa1 = wp[1];   // e = 2ep,   d 0..7
        float4 wb0 = wp[2], wb1 = wp[3];   // e = 2ep+1, d 0..7
        wp += 64;                          // advance 2 i

        uint64_t pw[8];
        pw[0] = pk(wa0.x, wb0.x); pw[1] = pk(wa0.y, wb0.y);
        pw[2] = pk(wa0.z, wb0.z); pw[3] = pk(wa0.w, wb0.w);
        pw[4] = pk(wa1.x, wb1.x); pw[5] = pk(wa1.y, wb1.y);
        pw[6] = pk(wa1.z, wb1.z); pw[7] = pk(wa1.w, wb1.w);

#pragma unroll
        for (int bb = 0; bb < 8; ++bb) {
            const uint64_t* xp = &sxs[bb][i][0];
            uint64_t acc = mul2(pw[0], xp[0]);
            fma2(acc, pw[1], xp[1]);
            fma2(acc, pw[2], xp[2]);
            fma2(acc, pw[3], xp[3]);
            fma2(acc, pw[4], xp[4]);
            fma2(acc, pw[5], xp[5]);
            fma2(acc, pw[6], xp[6]);
            fma2(acc, pw[7], xp[7]);
            add2(s0[bb], acc);
            float lo, hi; unpk(acc, lo, hi);
            __half2 h = __floats2half2_rn(lo, hi);
            *reinterpret_cast<__half2*>(
                &g_hat[((size_t)(b0 + bb) * NI + i0 + i) * 256 + n * 16 + 2 * ep]) = h;
        }
    }

    const int ch2 = blockIdx.x * 2 + islot;
#pragma unroll
    for (int bb = 0; bb < 8; ++bb) {
        float lo, hi; unpk(s0[bb], lo, hi);
        *reinterpret_cast<float2*>(
            &g_s0p[((size_t)ch2 * NB + b0 + bb) * 256 + n * 16 + 2 * ep])
            = make_float2(lo, hi);
    }
}

// squash along e via warp butterfly over low 4 lane bits (t = n*16+e)
__device__ __forceinline__ float squash_val(float sv) {
    float sq = sv * sv;
    sq += __shfl_xor_sync(0xffffffffu, sq, 1);
    sq += __shfl_xor_sync(0xffffffffu, sq, 2);
    sq += __shfl_xor_sync(0xffffffffu, sq, 4);
    sq += __shfl_xor_sync(0xffffffffu, sq, 8);
    float scale = sq / ((1.f + sq) * sqrtf(sq));
    return sv * scale;
}

// One i: fp16 hat fragment -> logit dot (packed), softmax over n (4 shfl),
// packed-fma accumulate into sacc.
__device__ __forceinline__ void step_i(uint4 A0, uint4 A1,
                                       const uint64_t vecp[8], uint64_t sacc[8]) {
    uint64_t fp[8];
    const __half2* ha = reinterpret_cast<const __half2*>(&A0);
#pragma unroll
    for (int j = 0; j < 4; ++j) { float2 v = __half22float2(ha[j]); fp[j] = pk(v.x, v.y); }
    const __half2* hb = reinterpret_cast<const __half2*>(&A1);
#pragma unroll
    for (int j = 0; j < 4; ++j) { float2 v = __half22float2(hb[j]); fp[4+j] = pk(v.x, v.y); }

    uint64_t dacc = mul2(vecp[0], fp[0]);
#pragma unroll
    for (int j = 1; j < 8; ++j) fma2(dacc, vecp[j], fp[j]);
    float dlo, dhi; unpk(dacc, dlo, dhi);
    float E = __expf(dlo + dhi);
    float den = E;
    den += __shfl_xor_sync(0xffffffffu, den, 1);
    den += __shfl_xor_sync(0xffffffffu, den, 2);
    den += __shfl_xor_sync(0xffffffffu, den, 4);
    den += __shfl_xor_sync(0xffffffffu, den, 8);
    float c = __fdividef(E, den);
    uint64_t cp = pk(c, c);
#pragma unroll
    for (int j = 0; j < 8; ++j) fma2(sacc[j], cp, fp[j]);
}

// One sweep over this CTA's i-split. Lane: n = lane&15, islot = lane>>4.
__device__ __forceinline__ void sweep(const uint4* p, const float* sVec,
                                      int n, int slot, float sRed[16][256]) {
    uint64_t vecp[8];
#pragma unroll
    for (int j = 0; j < 8; ++j)
        vecp[j] = pk(sVec[n * 16 + 2*j], sVec[n * 16 + 2*j + 1]);

    uint64_t sacc[8];
#pragma unroll
    for (int j = 0; j < 8; ++j) sacc[j] = 0ull;

    const int S = 16 * 32;
    uint4 A0 = p[0], A1 = p[1], B0 = p[S], B1 = p[S + 1];
    for (int s = 0; s < PSTEPS; s += 2) {
        uint4 C0, C1, D0, D1;
        if (s + 2 < PSTEPS) {
            C0 = p[2*S]; C1 = p[2*S + 1];
            D0 = p[3*S]; D1 = p[3*S + 1];
        }
        p += 2 * S;
        step_i(A0, A1, vecp, sacc);
        step_i(B0, B1, vecp, sacc);
        A0 = C0; A1 = C1; B0 = D0; B1 = D1;
    }
#pragma unroll
    for (int j = 0; j < 8; ++j) {
        float lo, hi; unpk(sacc[j], lo, hi);
        sRed[slot][n * 16 + 2*j]     = lo;
        sRed[slot][n * 16 + 2*j + 1] = hi;
    }
}

// ---------------------------------------------------------------------------
// k_route: everything after hat in ONE kernel. grid (128 b, 4 splits), 256 thr.
// head(out0) -> pass1 -> 4-CTA group barrier (per b) -> out1, vec -> pass2 ->
// last-CTA finalize (isp 0) + counter reset for graph replay determinism.
// __launch_bounds__(256,4): <=64 regs -> >=4 CTAs/SM -> all 512 co-resident.
// ---------------------------------------------------------------------------
__global__ void __launch_bounds__(256, 4) k_route(const float* __restrict__ Bias,
                                                  float* __restrict__ out) {
    __shared__ float sVec[256];
    __shared__ float sOut0[256];
    __shared__ float sRed[16][256];

    const int b = blockIdx.x, isp = blockIdx.y;
    const int t = threadIdx.x, warp = t >> 5, lane = t & 31;
    const int n = lane & 15, islot = lane >> 4;
    const int slot = warp * 2 + islot;
    const float bias = Bias[t];

    // ---- head: out0 = squash(sum_i hat /16 + Bias) ----
    {
        float sv = 0.f;
        for (int c = 0; c < ICH2; ++c)
            sv += g_s0p[((size_t)c * NB + b) * 256 + t];
        sv = sv * (1.f / 16.f) + bias;
        float o = squash_val(sv);
        sOut0[t] = o; sVec[t] = o;
    }
    __syncthreads();

    const uint4* p0 = reinterpret_cast<const uint4*>(g_hat)
                    + ((size_t)b * NI + isp * IPS + warp * 2 + islot) * 32 + n * 2;

    // ---- pass 1 ----
    sweep(p0, sVec, n, slot, sRed);
    __syncthreads();
    {
        float sv = 0.f;
#pragma unroll
        for (int w = 0; w < 16; ++w) sv += sRed[w][t];
        g_sp1[((size_t)isp * NB + b) * 256 + t] = sv;
    }
    __threadfence();
    __syncthreads();
    if (t == 0) {
        cnt_arrive(&g_cnt1[b]);
        while (cnt_ld(&g_cnt1[b]) < SPLIT) { }
    }
    __syncthreads();

    // ---- out1, telescoped vec = out0 + out1 ----
    {
        float sv = 0.f;
#pragma unroll
        for (int c = 0; c < SPLIT; ++c)
            sv += g_sp1[((size_t)c * NB + b) * 256 + t];
        sv += bias;
        sVec[t] = sOut0[t] + squash_val(sv);
    }
    __syncthreads();

    // ---- pass 2 ----
    sweep(p0, sVec, n, slot, sRed);
    __syncthreads();
    {
        float sv = 0.f;
#pragma unroll
        for (int w = 0; w < 16; ++w) sv += sRed[w][t];
        g_sp2[((size_t)isp * NB + b) * 256 + t] = sv;
    }
    __threadfence();
    __syncthreads();
    if (t == 0) cnt_arrive(&g_cnt2[b]);

    // ---- finalize (isp 0): wait for all splits, squash, write, reset ----
    if (isp == 0) {
        if (t == 0) { while (cnt_ld(&g_cnt2[b]) < SPLIT) { } }
        __syncthreads();
        float sv = 0.f;
#pragma unroll
        for (int c = 0; c < SPLIT; ++c)
            sv += g_sp2[((size_t)c * NB + b) * 256 + t];
        sv += bias;
        out[b * 256 + t] = squash_val(sv);
        if (t == 0) { g_cnt1[b] = 0; g_cnt2[b] = 0; }   // replay determinism
    }
}

extern "C" void kernel_launch(void* const* d_in, const int* in_sizes, int n_in,
                              void* d_out, int out_size) {
    const float* x    = (const float*)d_in[0];   // [128,1152,8]
    const float* W    = (const float*)d_in[1];   // [16,1152,16,8]
    const float* Bias = (const float*)d_in[2];   // [16,16]
    float* out = (float*)d_out;                  // [128,16,16]

    k_hat<<<dim3(ICHUNKS, NB / 8), 256>>>(x, W);   // 1152 CTAs
    k_route<<<dim3(NB, SPLIT), 256>>>(Bias, out);  // 512 CTAs, all co-resident
}

// round 6
// speedup vs baseline: 1.3514x; 1.3514x over previous
#include <cuda_runtime.h>
#include <cuda_fp16.h>
#include <stdint.h>
#include <math.h>

#define NB 128
#define NI 1152
#define IC 16                   // i per k_hat CTA
#define ICHUNKS (NI/IC)         // 72 (combined iter-0 partial chunks)
#define SPLIT 4                 // i-splits in routing passes
#define IPS (NI/SPLIT)          // 288
#define PSTEPS (IPS/16)         // 18 (16 i per CTA-step)

// Scratch (static device globals; no runtime allocation)
__device__ __half g_hat[(size_t)NB * NI * 256];   // [b][i][n*16+e], 75.5 MB
__device__ float  g_s0p[(size_t)ICHUNKS * NB * 256];
__device__ float  g_sp1[SPLIT * NB * 256];
__device__ float  g_sp2[SPLIT * NB * 256];
__device__ float  g_vec0[NB * 256];               // out0

// ---- packed f32x2 helpers (Blackwell FFMA2 via PTX) ----
__device__ __forceinline__ uint64_t pk(float a, float b) {
    uint64_t r; asm("mov.b64 %0, {%1,%2};" : "=l"(r) : "f"(a), "f"(b)); return r;
}
__device__ __forceinline__ void unpk(uint64_t v, float& lo, float& hi) {
    asm("mov.b64 {%0,%1}, %2;" : "=f"(lo), "=f"(hi) : "l"(v));
}
__device__ __forceinline__ uint64_t mul2(uint64_t a, uint64_t b) {
    uint64_t r; asm("mul.rn.f32x2 %0, %1, %2;" : "=l"(r) : "l"(a), "l"(b)); return r;
}
__device__ __forceinline__ void fma2(uint64_t& d, uint64_t a, uint64_t b) {
    asm("fma.rn.f32x2 %0, %1, %2, %3;" : "=l"(d) : "l"(a), "l"(b), "l"(d));
}
__device__ __forceinline__ void add2(uint64_t& d, uint64_t a) {
    asm("add.rn.f32x2 %0, %1, %2;" : "=l"(d) : "l"(a), "l"(d));
}

// ---------------------------------------------------------------------------
// k_hat: hat[b,i,n,e] = sum_d x[b,i,d]*W[n,i,e,d], fp16 out, e-pair packed.
// grid (72 i-chunks of 16, 16 b-blocks of 8). 256 threads:
//   t = islot*128 + n*8 + ep   (2 interleaved i's, 8 e-pairs)
// One STG.32 (half2) per (b,i) per thread. Iter-0 partials combined across
// islot in smem -> 72 chunks (halves the pass-1 head loads).
// ---------------------------------------------------------------------------
__global__ void __launch_bounds__(256) k_hat(const float* __restrict__ x,
                                             const float* __restrict__ W) {
    __shared__ uint64_t sxs[8][IC][8];   // splat (x,x), 8KB
    __shared__ float2   scmb[128][8];    // islot-combine staging, 8KB
    const int t  = threadIdx.x;
    const int i0 = blockIdx.x * IC;
    const int b0 = blockIdx.y * 8;

    for (int idx = t; idx < 8 * IC * 8; idx += 256) {
        int bb = idx >> 7, rem = idx & 127;
        int ii = rem >> 3, d = rem & 7;
        float v = x[((size_t)(b0 + bb) * NI + i0 + ii) * 8 + d];
        sxs[bb][ii][d] = pk(v, v);
    }
    __syncthreads();

    const int islot = t >> 7, r = t & 127;
    const int n = r >> 3, ep = r & 7;
    // W[n,i,e,d]: float4 idx ((n*NI+i)*16+e)*2 ; e=2ep,2ep+1 -> 4 consecutive f4
    const float4* wp = reinterpret_cast<const float4*>(W)
                     + ((size_t)(n * NI + i0 + islot) * 16 + 2 * ep) * 2;

    uint64_t s0[8];
#pragma unroll
    for (int k = 0; k < 8; ++k) s0[k] = 0ull;

    for (int i = islot; i < IC; i += 2) {
        float4 wa0 = wp[0], wa1 = wp[1];   // e = 2ep,   d 0..7
        float4 wb0 = wp[2], wb1 = wp[3];   // e = 2ep+1, d 0..7
        wp += 64;                          // advance 2 i

        uint64_t pw[8];
        pw[0] = pk(wa0.x, wb0.x); pw[1] = pk(wa0.y, wb0.y);
        pw[2] = pk(wa0.z, wb0.z); pw[3] = pk(wa0.w, wb0.w);
        pw[4] = pk(wa1.x, wb1.x); pw[5] = pk(wa1.y, wb1.y);
        pw[6] = pk(wa1.z, wb1.z); pw[7] = pk(wa1.w, wb1.w);

#pragma unroll
        for (int bb = 0; bb < 8; ++bb) {
            const uint64_t* xp = &sxs[bb][i][0];
            uint64_t acc = mul2(pw[0], xp[0]);
            fma2(acc, pw[1], xp[1]);
            fma2(acc, pw[2], xp[2]);
            fma2(acc, pw[3], xp[3]);
            fma2(acc, pw[4], xp[4]);
            fma2(acc, pw[5], xp[5]);
            fma2(acc, pw[6], xp[6]);
            fma2(acc, pw[7], xp[7]);
            add2(s0[bb], acc);
            float lo, hi; unpk(acc, lo, hi);
            __half2 h = __floats2half2_rn(lo, hi);
            *reinterpret_cast<__half2*>(
                &g_hat[((size_t)(b0 + bb) * NI + i0 + i) * 256 + n * 16 + 2 * ep]) = h;
        }
    }

    // combine islot partials -> one chunk per CTA
    __syncthreads();
    if (islot == 1) {
#pragma unroll
        for (int bb = 0; bb < 8; ++bb) {
            float lo, hi; unpk(s0[bb], lo, hi);
            scmb[r][bb] = make_float2(lo, hi);
        }
    }
    __syncthreads();
    if (islot == 0) {
#pragma unroll
        for (int bb = 0; bb < 8; ++bb) {
            float lo, hi; unpk(s0[bb], lo, hi);
            float2 o = scmb[r][bb];
            *reinterpret_cast<float2*>(
                &g_s0p[((size_t)blockIdx.x * NB + b0 + bb) * 256 + n * 16 + 2 * ep])
                = make_float2(lo + o.x, hi + o.y);
        }
    }
}

// squash along e via warp butterfly over low 4 lane bits (t = n*16+e)
__device__ __forceinline__ float squash_val(float sv) {
    float sq = sv * sv;
    sq += __shfl_xor_sync(0xffffffffu, sq, 1);
    sq += __shfl_xor_sync(0xffffffffu, sq, 2);
    sq += __shfl_xor_sync(0xffffffffu, sq, 4);
    sq += __shfl_xor_sync(0xffffffffu, sq, 8);
    float scale = sq / ((1.f + sq) * sqrtf(sq));
    return sv * scale;
}

// One i: fp16 hat fragment -> logit dot (packed), softmax over n (4 shfl),
// packed-fma accumulate into sacc.
__device__ __forceinline__ void step_i(uint4 A0, uint4 A1,
                                       const uint64_t vecp[8], uint64_t sacc[8]) {
    uint64_t fp[8];
    const __half2* ha = reinterpret_cast<const __half2*>(&A0);
#pragma unroll
    for (int j = 0; j < 4; ++j) { float2 v = __half22float2(ha[j]); fp[j] = pk(v.x, v.y); }
    const __half2* hb = reinterpret_cast<const __half2*>(&A1);
#pragma unroll
    for (int j = 0; j < 4; ++j) { float2 v = __half22float2(hb[j]); fp[4+j] = pk(v.x, v.y); }

    uint64_t dacc = mul2(vecp[0], fp[0]);
#pragma unroll
    for (int j = 1; j < 8; ++j) fma2(dacc, vecp[j], fp[j]);
    float dlo, dhi; unpk(dacc, dlo, dhi);
    float E = __expf(dlo + dhi);
    float den = E;
    den += __shfl_xor_sync(0xffffffffu, den, 1);
    den += __shfl_xor_sync(0xffffffffu, den, 2);
    den += __shfl_xor_sync(0xffffffffu, den, 4);
    den += __shfl_xor_sync(0xffffffffu, den, 8);
    float c = __fdividef(E, den);
    uint64_t cp = pk(c, c);
#pragma unroll
    for (int j = 0; j < 8; ++j) fma2(sacc[j], cp, fp[j]);
}

// ---------------------------------------------------------------------------
// k_pass: fused head (build vec from partials) + one routing sweep.
// stage 1: vec = out0 = squash(sum_i hat /16 + Bias)  [from g_s0p]
// stage 2: vec = out0 + out1                          [g_vec0, g_sp1]
// Thread-per-(i,n): lane l -> n = l&15, islot = l>>4. grid (128, SPLIT).
// NO min-blocks bound: let ptxas use the registers it needs (R5 lesson).
// ---------------------------------------------------------------------------
__global__ void __launch_bounds__(256) k_pass(const float* __restrict__ Bias,
                                              int stage) {
    __shared__ float sVec[256];
    __shared__ float sRed[16][256];

    const int b = blockIdx.x, isp = blockIdx.y;
    const int t = threadIdx.x, warp = t >> 5, lane = t & 31;
    const int n = lane & 15, islot = lane >> 4;

    // --- head: build vec for this batch (redundant per CTA, cheap) ---
    {
        float sv = 0.f;
        if (stage == 1) {
            for (int c = 0; c < ICHUNKS; ++c)
                sv += g_s0p[((size_t)c * NB + b) * 256 + t];
            sv = sv * (1.f / 16.f) + Bias[t];
            float o = squash_val(sv);
            sVec[t] = o;
            if (isp == 0) g_vec0[b * 256 + t] = o;
        } else {
#pragma unroll
            for (int c = 0; c < SPLIT; ++c)
                sv += g_sp1[((size_t)c * NB + b) * 256 + t];
            sv += Bias[t];
            sVec[t] = g_vec0[b * 256 + t] + squash_val(sv);
        }
    }
    __syncthreads();

    uint64_t vecp[8];
#pragma unroll
    for (int j = 0; j < 8; ++j)
        vecp[j] = pk(sVec[n * 16 + 2*j], sVec[n * 16 + 2*j + 1]);

    const int iStart = isp * IPS + warp * 2 + islot;
    const uint4* p = reinterpret_cast<const uint4*>(g_hat)
                   + ((size_t)b * NI + iStart) * 32 + n * 2;
    const int S = 16 * 32;   // 16 i per CTA-step, 32 uint4 per i

    uint64_t sacc[8];
#pragma unroll
    for (int j = 0; j < 8; ++j) sacc[j] = 0ull;

    // 2-step unroll, 4 LDG.128 in flight per lane
    uint4 A0 = p[0], A1 = p[1], B0 = p[S], B1 = p[S + 1];
    for (int s = 0; s < PSTEPS; s += 2) {
        uint4 C0, C1, D0, D1;
        if (s + 2 < PSTEPS) {
            C0 = p[2 * S]; C1 = p[2 * S + 1];
            D0 = p[3 * S]; D1 = p[3 * S + 1];
        }
        p += 2 * S;
        step_i(A0, A1, vecp, sacc);
        step_i(B0, B1, vecp, sacc);
        A0 = C0; A1 = C1; B0 = D0; B1 = D1;
    }

    const int slot = warp * 2 + islot;
#pragma unroll
    for (int j = 0; j < 8; ++j) {
        float lo, hi; unpk(sacc[j], lo, hi);
        sRed[slot][n * 16 + 2*j]     = lo;
        sRed[slot][n * 16 + 2*j + 1] = hi;
    }
    __syncthreads();

    float sv = 0.f;
#pragma unroll
    for (int w = 0; w < 16; ++w) sv += sRed[w][t];
    float* dst = (stage == 1) ? g_sp1 : g_sp2;
    dst[((size_t)isp * NB + b) * 256 + t] = sv;
}

// ---------------------------------------------------------------------------
// k_final: out = squash(sum_split g_sp2 + Bias). grid 128, 256 threads.
// ---------------------------------------------------------------------------
__global__ void __launch_bounds__(256) k_final(const float* __restrict__ Bias,
                                               float* __restrict__ out) {
    const int b = blockIdx.x, t = threadIdx.x;
    float sv = 0.f;
#pragma unroll
    for (int c = 0; c < SPLIT; ++c)
        sv += g_sp2[((size_t)c * NB + b) * 256 + t];
    sv += Bias[t];
    out[b * 256 + t] = squash_val(sv);
}

extern "C" void kernel_launch(void* const* d_in, const int* in_sizes, int n_in,
                              void* d_out, int out_size) {
    const float* x    = (const float*)d_in[0];   // [128,1152,8]
    const float* W    = (const float*)d_in[1];   // [16,1152,16,8]
    const float* Bias = (const float*)d_in[2];   // [16,16]
    float* out = (float*)d_out;                  // [128,16,16]

    k_hat<<<dim3(ICHUNKS, NB / 8), 256>>>(x, W);   // 1152 CTAs
    k_pass<<<dim3(NB, SPLIT), 256>>>(Bias, 1);     // pass 1
    k_pass<<<dim3(NB, SPLIT), 256>>>(Bias, 2);     // pass 2 (telescoped)
    k_final<<<NB, 256>>>(Bias, out);
}